// round 15
// baseline (speedup 1.0000x reference)
#include <cuda_runtime.h>
#include <cuda_bf16.h>
#include <math.h>
#include <stdint.h>

#define N_SPK 1024
#define M_UTT 32
#define D_DIM 512
#define R_ROWS (N_SPK * M_UTT)
#define EPS 1e-6f
#define LOG2E 1.4426950408889634f
#define LN2F 0.6931471805599453f
#define SA 25.0f                      // A quant scale (range +-5.08)
#define SC 127.0f                     // C quant scale
#define INV_DOT (1.0f / (SA * SC))

// ---------------- device scratch (no allocations allowed) ----------------
__device__ uint8_t g_A8[R_ROWS * D_DIM];          // 16 MB  int8 dvecs (x25)
__device__ uint8_t g_C8[N_SPK * D_DIM];           // 0.5 MB int8 centroids (x127)
__device__ float g_csq[N_SPK];
__device__ float g_cinv[N_SPK];
__device__ float g_esq[R_ROWS];
__device__ float g_einv[R_ROWS];
__device__ float g_Zp[8 * R_ROWS];                // per-col-tile softmax partials
__device__ float g_own[R_ROWS];                   // own-speaker w*cos*log2e
__device__ float g_bsum[128];                     // loss block partials
__device__ unsigned int g_count = 0;              // completion counter

// ---------------- PTX helpers ----------------
__device__ __forceinline__ uint32_t smem_u32(const void* p) {
    uint32_t a;
    asm("{ .reg .u64 t; cvta.to.shared.u64 t, %1; cvt.u32.u64 %0, t; }" : "=r"(a) : "l"(p));
    return a;
}
__device__ __forceinline__ void cp_async16(uint32_t dst, const void* src) {
    asm volatile("cp.async.cg.shared.global.L2::128B [%0], [%1], 16;\n" :: "r"(dst), "l"(src));
}
__device__ __forceinline__ void cp_commit() {
    asm volatile("cp.async.commit_group;\n" ::: "memory");
}
template <int N>
__device__ __forceinline__ void cp_wait() {
    asm volatile("cp.async.wait_group %0;\n" :: "n"(N) : "memory");
}
__device__ __forceinline__ void ldmx4(uint32_t* r, uint32_t addr) {
    asm volatile("ldmatrix.sync.aligned.m8n8.x4.shared.b16 {%0,%1,%2,%3}, [%4];"
                 : "=r"(r[0]), "=r"(r[1]), "=r"(r[2]), "=r"(r[3]) : "r"(addr));
}
// int8 IMMA: m16n8k32, s32 accumulate
__device__ __forceinline__ void mma_s8(int* c, const uint32_t* a, uint32_t b0, uint32_t b1) {
    asm volatile(
        "mma.sync.aligned.m16n8k32.row.col.s32.s8.s8.s32 "
        "{%0,%1,%2,%3}, {%4,%5,%6,%7}, {%8,%9}, {%0,%1,%2,%3};"
        : "+r"(c[0]), "+r"(c[1]), "+r"(c[2]), "+r"(c[3])
        : "r"(a[0]), "r"(a[1]), "r"(a[2]), "r"(a[3]), "r"(b0), "r"(b1));
}
__device__ __forceinline__ uint32_t swz(uint32_t bo) {   // SW128: bits[4:6] ^= bits[7:9]
    return bo ^ ((bo >> 3) & 0x70);
}
// saturating pack of 4 scaled floats -> 4 x s8 (byte0 = x)
__device__ __forceinline__ uint32_t packs8x4(float4 v, float s) {
    int ia = __float2int_rn(v.x * s);
    int ib = __float2int_rn(v.y * s);
    int ic = __float2int_rn(v.z * s);
    int id = __float2int_rn(v.w * s);
    uint32_t t, r;
    asm("cvt.pack.sat.s8.s32.b32 %0, %1, %2, %3;" : "=r"(t) : "r"(id), "r"(ic), "r"(0));
    asm("cvt.pack.sat.s8.s32.b32 %0, %1, %2, %3;" : "=r"(r) : "r"(ib), "r"(ia), "r"(t));
    return r;
}
__device__ __forceinline__ uint16_t packs8x2(float x, float y, float s) {
    int ia = __float2int_rn(x * s);
    int ib = __float2int_rn(y * s);
    uint32_t t;
    asm("cvt.pack.sat.s8.s32.b32 %0, %1, %2, %3;" : "=r"(t) : "r"(ib), "r"(ia), "r"(0));
    return (uint16_t)t;
}

// fast 2^x on the FMA pipe, x in ~[-8, 8]
__device__ __forceinline__ float exp2_fast(float x) {
    float z = x + 12582912.0f;                 // round-to-nearest via magic constant
    float f = x - (z - 12582912.0f);           // f in [-0.5, 0.5]
    int   n = __float_as_int(z) - 0x4B400000;
    float p = 0.001333355814642844f;
    p = fmaf(p, f, 0.009618129107628477f);
    p = fmaf(p, f, 0.055504108664821580f);
    p = fmaf(p, f, 0.240226506959100700f);
    p = fmaf(p, f, 0.693147180559945300f);
    p = fmaf(p, f, 1.0f);
    float s = __int_as_float((n + 127) << 23);
    return p * s;
}

// ---------------------------------------------------------------------------
// Kernel 1: fused prep. One block per speaker (256 thr, 8 warps x 4 rows).
// R15: reg budget raised to 64 (occ 4) + paired-row load batching for MLP.
// ---------------------------------------------------------------------------
__global__ void __launch_bounds__(256, 4) prep_kernel(const float* __restrict__ dvecs) {
    __shared__ float shc[8][512];
    __shared__ float shr[256];

    const int j    = blockIdx.x;
    const int tid  = threadIdx.x;
    const int wid  = tid >> 5;
    const int lane = tid & 31;

    const float4* base = (const float4*)(dvecs + (size_t)j * M_UTT * D_DIM);

    float4 csum[4];
#pragma unroll
    for (int k = 0; k < 4; k++) csum[k] = make_float4(0.f, 0.f, 0.f, 0.f);
    float s[4] = {0.f, 0.f, 0.f, 0.f};

#pragma unroll
    for (int rp = 0; rp < 2; rp++) {               // pairs of rows
        const int m0 = wid * 4 + rp * 2;
        const int r0 = rp * 2, r1 = rp * 2 + 1;
        const float4* src0 = base + (size_t)m0 * 128;
        const float4* src1 = base + (size_t)(m0 + 1) * 128;

        // batch 8 independent loads before any consume (MLP)
        float4 v0[4], v1[4];
#pragma unroll
        for (int k = 0; k < 4; k++) v0[k] = src0[lane + k * 32];
#pragma unroll
        for (int k = 0; k < 4; k++) v1[k] = src1[lane + k * 32];

        uint32_t* dst0 = (uint32_t*)(g_A8 + (size_t)(j * M_UTT + m0) * D_DIM);
        uint32_t* dst1 = (uint32_t*)(g_A8 + (size_t)(j * M_UTT + m0 + 1) * D_DIM);
#pragma unroll
        for (int k = 0; k < 4; k++) {
            float4 v = v0[k];
            s[r0] = fmaf(v.x, v.x, fmaf(v.y, v.y, fmaf(v.z, v.z, fmaf(v.w, v.w, s[r0]))));
            csum[k].x += v.x; csum[k].y += v.y;
            csum[k].z += v.z; csum[k].w += v.w;
            dst0[lane + k * 32] = packs8x4(v, SA);
        }
#pragma unroll
        for (int k = 0; k < 4; k++) {
            float4 v = v1[k];
            s[r1] = fmaf(v.x, v.x, fmaf(v.y, v.y, fmaf(v.z, v.z, fmaf(v.w, v.w, s[r1]))));
            csum[k].x += v.x; csum[k].y += v.y;
            csum[k].z += v.z; csum[k].w += v.w;
            dst1[lane + k * 32] = packs8x4(v, SA);
        }
    }

    // deferred per-row norm reductions
#pragma unroll
    for (int r = 0; r < 4; r++) {
        float t = s[r];
#pragma unroll
        for (int off = 16; off > 0; off >>= 1) t += __shfl_xor_sync(0xffffffffu, t, off);
        if (lane == 0) {
            const int row = j * M_UTT + wid * 4 + r;
            g_esq[row]  = t;
            g_einv[row] = rsqrtf(t);
        }
    }

    float4* myrow = (float4*)shc[wid];
#pragma unroll
    for (int k = 0; k < 4; k++) myrow[lane + k * 32] = csum[k];
    __syncthreads();

    float2 tot = make_float2(0.f, 0.f);
#pragma unroll
    for (int w = 0; w < 8; w++) {
        float2 v = ((float2*)shc[w])[tid];
        tot.x += v.x;
        tot.y += v.y;
    }
    float cx = tot.x * (1.0f / M_UTT);
    float cy = tot.y * (1.0f / M_UTT);
    ((uint16_t*)(g_C8 + (size_t)j * D_DIM))[tid] = packs8x2(cx, cy, SC);

    shr[tid] = cx * cx + cy * cy;
    __syncthreads();
    for (int off = 128; off > 0; off >>= 1) {
        if (tid < off) shr[tid] += shr[tid + off];
        __syncthreads();
    }
    if (tid == 0) {
        g_csq[j]  = shr[0];
        g_cinv[j] = rsqrtf(shr[0]);
    }
}

// ---------------------------------------------------------------------------
// Kernel 2: int8 IMMA GEMM + branchless softmax epilogue (R14 — unchanged).
// ---------------------------------------------------------------------------
#define STAGES 3
#define A_BYTES 16384
#define B_BYTES 16384
#define STAGE_BYTES (A_BYTES + B_BYTES)
#define OFF_EINV  0
#define OFF_ESQ   512
#define OFF_CINV  1024
#define OFF_CSQ   1536
#define OFF_PART  2048                 // 4 x 128 floats
#define OFF_STAGE 4096
#define SMEM_TOTAL (OFF_STAGE + STAGES * STAGE_BYTES)   // 102400

__global__ void __launch_bounds__(256, 2)
gemm_loss_kernel(const float* __restrict__ wp) {
    extern __shared__ char smem[];
    const uint32_t sb = smem_u32(smem);
    const int tid  = threadIdx.x;
    const int wid  = tid >> 5;
    const int lane = tid & 31;
    const int wy   = wid >> 2;          // 0..1  (64-row slice)
    const int wx   = wid & 3;           // 0..3  (32-col slice)
    const int col0 = blockIdx.x * 128;
    const int row0 = blockIdx.y * 128;

    float* sh_einv = (float*)(smem + OFF_EINV);
    float* sh_esq  = (float*)(smem + OFF_ESQ);
    float* sh_cinv = (float*)(smem + OFF_CINV);
    float* sh_csq  = (float*)(smem + OFF_CSQ);
    float* sh_part = (float*)(smem + OFF_PART);

    if (tid < 128) {
        sh_einv[tid] = g_einv[row0 + tid];
        sh_esq[tid]  = g_esq[row0 + tid];
        sh_cinv[tid] = g_cinv[col0 + tid];
        sh_csq[tid]  = g_csq[col0 + tid];
    }

    const char* Ag0 = (const char*)(g_A8 + (size_t)row0 * D_DIM);
    const char* Bg0 = (const char*)(g_C8 + (size_t)col0 * D_DIM);
    auto load_stage = [&](int kt, int s) {
        uint32_t abase = sb + OFF_STAGE + s * STAGE_BYTES;
        uint32_t bbase = abase + A_BYTES;
        const char* Ag = Ag0 + kt * 128;
        const char* Bg = Bg0 + kt * 128;
#pragma unroll
        for (int t = 0; t < 4; t++) {
            int ch = tid + t * 256;
            int r = ch >> 3, c = ch & 7;
            uint32_t bo = r * 128 + c * 16;
            cp_async16(abase + swz(bo), Ag + (size_t)r * 512 + c * 16);
        }
#pragma unroll
        for (int t = 0; t < 4; t++) {
            int ch = tid + t * 256;
            int r = ch >> 3, c = ch & 7;
            uint32_t bo = r * 128 + c * 16;
            cp_async16(bbase + swz(bo), Bg + (size_t)r * 512 + c * 16);
        }
        cp_commit();
    };

    load_stage(0, 0);
    load_stage(1, 1);

    int acc[4][4][4];
#pragma unroll
    for (int i = 0; i < 4; i++)
#pragma unroll
        for (int j = 0; j < 4; j++)
#pragma unroll
            for (int k = 0; k < 4; k++) acc[i][j][k] = 0;

    const int lrow = lane & 15;
    const int lc16 = lane >> 4;
    const uint32_t aoff0 = (wy * 64 + lrow) * 128 + lc16 * 16;
    const uint32_t boff0 = (wx * 32 + lrow) * 128 + lc16 * 16;

#pragma unroll 1
    for (int kt = 0; kt < 4; kt++) {
        const int s = kt % STAGES;
        if (kt < 3) cp_wait<1>(); else cp_wait<0>();
        __syncthreads();

        uint32_t abase = sb + OFF_STAGE + s * STAGE_BYTES;
        uint32_t bbase = abase + A_BYTES;
#pragma unroll
        for (int kg = 0; kg < 4; kg++) {
            uint32_t a[4][4], b[2][4];
#pragma unroll
            for (int mt = 0; mt < 4; mt++)
                ldmx4(a[mt], abase + swz(aoff0 + mt * 2048 + kg * 32));
#pragma unroll
            for (int nb = 0; nb < 2; nb++)
                ldmx4(b[nb], bbase + swz(boff0 + nb * 2048 + kg * 32));
#pragma unroll
            for (int mt = 0; mt < 4; mt++)
#pragma unroll
                for (int nt = 0; nt < 4; nt++)
                    mma_s8(acc[mt][nt], a[mt], b[nt >> 1][nt & 1], b[nt >> 1][(nt & 1) + 2]);
        }

        if (kt + 2 < 4) load_stage(kt + 2, (kt + 2) % STAGES);
        else cp_commit();
    }
    __syncthreads();

    // ---- branchless softmax epilogue ----
    const float wv     = *wp;
    const float wl2    = wv * LOG2E;
    const float clamp2 = EPS * wl2;

    float tc2[8];
#pragma unroll
    for (int nt = 0; nt < 4; nt++)
#pragma unroll
        for (int j = 0; j < 2; j++) {
            int cl = wx * 32 + nt * 8 + (lane & 3) * 2 + j;
            tc2[nt * 2 + j] = sh_cinv[cl] * wl2 * INV_DOT;
        }

    // own-speaker columns live in this CTA iff col tile == row block's speaker range
    const bool fixcta = ((int)blockIdx.x == ((int)blockIdx.y >> 5));

    float* part = sh_part + wx * 128;

#pragma unroll
    for (int mt = 0; mt < 4; mt++) {
#pragma unroll
        for (int half = 0; half < 2; half++) {
            int   rl   = wy * 64 + mt * 16 + (lane >> 2) + half * 8;
            float einv = sh_einv[rl];

            float rsum = 0.f;
#pragma unroll
            for (int nt = 0; nt < 4; nt++) {
#pragma unroll
                for (int j = 0; j < 2; j++) {
                    float v = __int2float_rn(acc[mt][nt][half * 2 + j]);
                    float u = fmaxf((v * einv) * tc2[nt * 2 + j], clamp2);
                    rsum += exp2_fast(u);
                }
            }

            if (fixcta) {
                int r   = row0 + rl;
                int clt = (r >> 5) - col0;        // target own column (0..127)
#pragma unroll
                for (int nt = 0; nt < 4; nt++) {
#pragma unroll
                    for (int j = 0; j < 2; j++) {
                        int cl_e = wx * 32 + nt * 8 + (lane & 3) * 2 + j;
                        if (cl_e == clt) {        // compile-time acc indices only
                            float v  = __int2float_rn(acc[mt][nt][half * 2 + j]);
                            float up = fmaxf((v * einv) * tc2[nt * 2 + j], clamp2);
                            float esq  = sh_esq[rl];
                            float vv   = v * INV_DOT;
                            float dl   = fmaf(32.f, vv, -esq) * (1.f / 31.f);
                            float clq  = (1024.f * sh_csq[clt] - 64.f * vv + esq) * (1.f / 961.f);
                            float cosv = dl * einv * rsqrtf(clq);
                            float u    = fmaxf(cosv * wl2, clamp2);
                            g_own[r]   = u;
                            rsum += exp2_fast(u) - exp2_fast(up);
                        }
                    }
                }
            }

            rsum += __shfl_xor_sync(0xffffffffu, rsum, 1);
            rsum += __shfl_xor_sync(0xffffffffu, rsum, 2);
            if ((lane & 3) == 0) part[rl] = rsum;
        }
    }
    __syncthreads();

    if (tid < 128) {
        g_Zp[(size_t)blockIdx.x * R_ROWS + row0 + tid] =
            sh_part[tid] + sh_part[128 + tid] + sh_part[256 + tid] + sh_part[384 + tid];
    }
}

// ---------------------------------------------------------------------------
// Kernel 3: single-launch loss reduction. 128 blocks x 256 threads.
// ---------------------------------------------------------------------------
__global__ void __launch_bounds__(256) loss_kernel(float* __restrict__ out) {
    const int tid = threadIdx.x;
    const int r   = blockIdx.x * 256 + tid;
    float z = 0.f;
#pragma unroll
    for (int p = 0; p < 8; p++) z += g_Zp[(size_t)p * R_ROWS + r];
    float s = logf(z) - g_own[r] * LN2F;

    __shared__ float sh[256];
    __shared__ bool  last;
    sh[tid] = s;
    __syncthreads();
    for (int off = 128; off > 0; off >>= 1) {
        if (tid < off) sh[tid] += sh[tid + off];
        __syncthreads();
    }
    if (tid == 0) {
        g_bsum[blockIdx.x] = sh[0];
        __threadfence();
        unsigned int t = atomicAdd(&g_count, 1u);
        last = (t == 127u);
    }
    __syncthreads();

    if (last) {
        float v = (tid < 128) ? g_bsum[tid] : 0.f;
#pragma unroll
        for (int off = 16; off > 0; off >>= 1) v += __shfl_xor_sync(0xffffffffu, v, off);
        __shared__ float sh2[8];
        if ((tid & 31) == 0) sh2[tid >> 5] = v;
        __syncthreads();
        if (tid == 0) {
            out[0] = sh2[0] + sh2[1] + sh2[2] + sh2[3];
            g_count = 0;                       // reset for next graph replay
        }
    }
}

// ---------------------------------------------------------------------------
extern "C" void kernel_launch(void* const* d_in, const int* in_sizes, int n_in,
                              void* d_out, int out_size) {
    const float* dvecs = (const float*)d_in[0];
    const float* w     = (const float*)d_in[1];
    float* out         = (float*)d_out;

    cudaFuncSetAttribute(gemm_loss_kernel,
                         cudaFuncAttributeMaxDynamicSharedMemorySize, SMEM_TOTAL);

    prep_kernel<<<N_SPK, 256>>>(dvecs);
    gemm_loss_kernel<<<dim3(8, 256), 256, SMEM_TOTAL>>>(w);
    loss_kernel<<<128, 256>>>(out);
}

// round 16
// speedup vs baseline: 1.0004x; 1.0004x over previous
#include <cuda_runtime.h>
#include <cuda_bf16.h>
#include <math.h>
#include <stdint.h>

#define N_SPK 1024
#define M_UTT 32
#define D_DIM 512
#define R_ROWS (N_SPK * M_UTT)
#define EPS 1e-6f
#define LOG2E 1.4426950408889634f
#define LN2F 0.6931471805599453f
#define SA 25.0f                      // A quant scale (range +-5.08)
#define SC 127.0f                     // C quant scale
#define INV_DOT (1.0f / (SA * SC))

// ---------------- device scratch (no allocations allowed) ----------------
__device__ uint8_t g_A8[R_ROWS * D_DIM];          // 16 MB  int8 dvecs (x25)
__device__ uint8_t g_C8[N_SPK * D_DIM];           // 0.5 MB int8 centroids (x127)
__device__ float g_csq[N_SPK];
__device__ float g_cinv[N_SPK];
__device__ float g_esq[R_ROWS];
__device__ float g_einv[R_ROWS];
__device__ float g_Zp[8 * R_ROWS];                // per-col-tile softmax partials
__device__ float g_own[R_ROWS];                   // own-speaker w*cos*log2e
__device__ float g_bsum[128];                     // loss block partials
__device__ unsigned int g_count = 0;              // completion counter

// ---------------- PTX helpers ----------------
__device__ __forceinline__ uint32_t smem_u32(const void* p) {
    uint32_t a;
    asm("{ .reg .u64 t; cvta.to.shared.u64 t, %1; cvt.u32.u64 %0, t; }" : "=r"(a) : "l"(p));
    return a;
}
__device__ __forceinline__ void cp_async16(uint32_t dst, const void* src) {
    asm volatile("cp.async.cg.shared.global.L2::128B [%0], [%1], 16;\n" :: "r"(dst), "l"(src));
}
__device__ __forceinline__ void cp_commit() {
    asm volatile("cp.async.commit_group;\n" ::: "memory");
}
template <int N>
__device__ __forceinline__ void cp_wait() {
    asm volatile("cp.async.wait_group %0;\n" :: "n"(N) : "memory");
}
__device__ __forceinline__ void ldmx4(uint32_t* r, uint32_t addr) {
    asm volatile("ldmatrix.sync.aligned.m8n8.x4.shared.b16 {%0,%1,%2,%3}, [%4];"
                 : "=r"(r[0]), "=r"(r[1]), "=r"(r[2]), "=r"(r[3]) : "r"(addr));
}
// int8 IMMA: m16n8k32, s32 accumulate
__device__ __forceinline__ void mma_s8(int* c, const uint32_t* a, uint32_t b0, uint32_t b1) {
    asm volatile(
        "mma.sync.aligned.m16n8k32.row.col.s32.s8.s8.s32 "
        "{%0,%1,%2,%3}, {%4,%5,%6,%7}, {%8,%9}, {%0,%1,%2,%3};"
        : "+r"(c[0]), "+r"(c[1]), "+r"(c[2]), "+r"(c[3])
        : "r"(a[0]), "r"(a[1]), "r"(a[2]), "r"(a[3]), "r"(b0), "r"(b1));
}
__device__ __forceinline__ uint32_t swz(uint32_t bo) {   // SW128: bits[4:6] ^= bits[7:9]
    return bo ^ ((bo >> 3) & 0x70);
}
// saturating pack of 4 scaled floats -> 4 x s8 (byte0 = x)
__device__ __forceinline__ uint32_t packs8x4(float4 v, float s) {
    int ia = __float2int_rn(v.x * s);
    int ib = __float2int_rn(v.y * s);
    int ic = __float2int_rn(v.z * s);
    int id = __float2int_rn(v.w * s);
    uint32_t t, r;
    asm("cvt.pack.sat.s8.s32.b32 %0, %1, %2, %3;" : "=r"(t) : "r"(id), "r"(ic), "r"(0));
    asm("cvt.pack.sat.s8.s32.b32 %0, %1, %2, %3;" : "=r"(r) : "r"(ib), "r"(ia), "r"(t));
    return r;
}
__device__ __forceinline__ uint16_t packs8x2(float x, float y, float s) {
    int ia = __float2int_rn(x * s);
    int ib = __float2int_rn(y * s);
    uint32_t t;
    asm("cvt.pack.sat.s8.s32.b32 %0, %1, %2, %3;" : "=r"(t) : "r"(ib), "r"(ia), "r"(0));
    return (uint16_t)t;
}

// fast 2^x on the FMA pipe, x in ~[-8, 8]
__device__ __forceinline__ float exp2_fast(float x) {
    float z = x + 12582912.0f;                 // round-to-nearest via magic constant
    float f = x - (z - 12582912.0f);           // f in [-0.5, 0.5]
    int   n = __float_as_int(z) - 0x4B400000;
    float p = 0.001333355814642844f;
    p = fmaf(p, f, 0.009618129107628477f);
    p = fmaf(p, f, 0.055504108664821580f);
    p = fmaf(p, f, 0.240226506959100700f);
    p = fmaf(p, f, 0.693147180559945300f);
    p = fmaf(p, f, 1.0f);
    float s = __int_as_float((n + 127) << 23);
    return p * s;
}

// ---------------------------------------------------------------------------
// Kernel 1: fused prep via cp.async staging. One block per speaker, 256 thr.
// 4 stages x 8 rows x 2KB fp32 loaded with deep async queue (no RF pressure),
// consumed warp-per-row from smem. Tail reductions overlay the stage buffer.
// ---------------------------------------------------------------------------
#define P_STAGE_BYTES 16384            // 8 rows x 2048 B
#define P_SMEM_TOTAL  65536            // 4 stages

__global__ void __launch_bounds__(256) prep_kernel(const float* __restrict__ dvecs) {
    extern __shared__ char psm[];
    const uint32_t sb = smem_u32(psm);

    const int j    = blockIdx.x;
    const int tid  = threadIdx.x;
    const int wid  = tid >> 5;
    const int lane = tid & 31;

    const char* gsrc = (const char*)(dvecs + (size_t)j * M_UTT * D_DIM);

    // issue all 4 stage loads up front (deep async queue)
#pragma unroll
    for (int s = 0; s < 4; s++) {
#pragma unroll
        for (int t = 0; t < 4; t++) {
            int idx = tid + t * 256;            // 1024 x 16B chunks per stage
            cp_async16(sb + s * P_STAGE_BYTES + idx * 16,
                       gsrc + (size_t)s * P_STAGE_BYTES + idx * 16);
        }
        cp_commit();
    }

    float4 csum[4];
#pragma unroll
    for (int k = 0; k < 4; k++) csum[k] = make_float4(0.f, 0.f, 0.f, 0.f);
    float nrm[4] = {0.f, 0.f, 0.f, 0.f};

    // consume stage s: warp w handles row 8s + w
#pragma unroll
    for (int s = 0; s < 4; s++) {
        if (s == 0) cp_wait<3>();
        else if (s == 1) cp_wait<2>();
        else if (s == 2) cp_wait<1>();
        else cp_wait<0>();
        __syncthreads();

        const int m = s * 8 + wid;
        const float4* srow = (const float4*)(psm + s * P_STAGE_BYTES + wid * 2048);
        uint32_t* dst = (uint32_t*)(g_A8 + (size_t)(j * M_UTT + m) * D_DIM);
#pragma unroll
        for (int k = 0; k < 4; k++) {
            float4 v = srow[lane + k * 32];
            nrm[s] = fmaf(v.x, v.x, fmaf(v.y, v.y, fmaf(v.z, v.z, fmaf(v.w, v.w, nrm[s]))));
            csum[k].x += v.x; csum[k].y += v.y;
            csum[k].z += v.z; csum[k].w += v.w;
            dst[lane + k * 32] = packs8x4(v, SA);
        }
    }

    // per-row norm reductions (warp w owns rows 8s+w)
#pragma unroll
    for (int s = 0; s < 4; s++) {
        float t = nrm[s];
#pragma unroll
        for (int off = 16; off > 0; off >>= 1) t += __shfl_xor_sync(0xffffffffu, t, off);
        if (lane == 0) {
            const int row = j * M_UTT + s * 8 + wid;
            g_esq[row]  = t;
            g_einv[row] = rsqrtf(t);
        }
    }
    __syncthreads();                   // all stage reads done -> overlay safe

    // centroid: per-warp partials into overlay smem (stage-0/1 region reused)
    float* shc = (float*)psm;          // 8 x 512 floats = 16 KB
    float* shr = (float*)(psm + 16384);
    float4* myrow = (float4*)(shc + wid * 512);
#pragma unroll
    for (int k = 0; k < 4; k++) myrow[lane + k * 32] = csum[k];
    __syncthreads();

    float2 tot = make_float2(0.f, 0.f);
#pragma unroll
    for (int w = 0; w < 8; w++) {
        float2 v = ((float2*)(shc + w * 512))[tid];
        tot.x += v.x;
        tot.y += v.y;
    }
    float cx = tot.x * (1.0f / M_UTT);
    float cy = tot.y * (1.0f / M_UTT);
    ((uint16_t*)(g_C8 + (size_t)j * D_DIM))[tid] = packs8x2(cx, cy, SC);

    shr[tid] = cx * cx + cy * cy;
    __syncthreads();
    for (int off = 128; off > 0; off >>= 1) {
        if (tid < off) shr[tid] += shr[tid + off];
        __syncthreads();
    }
    if (tid == 0) {
        g_csq[j]  = shr[0];
        g_cinv[j] = rsqrtf(shr[0]);
    }
}

// ---------------------------------------------------------------------------
// Kernel 2: int8 IMMA GEMM + branchless softmax epilogue (R14 — unchanged).
// ---------------------------------------------------------------------------
#define STAGES 3
#define A_BYTES 16384
#define B_BYTES 16384
#define STAGE_BYTES (A_BYTES + B_BYTES)
#define OFF_EINV  0
#define OFF_ESQ   512
#define OFF_CINV  1024
#define OFF_CSQ   1536
#define OFF_PART  2048                 // 4 x 128 floats
#define OFF_STAGE 4096
#define SMEM_TOTAL (OFF_STAGE + STAGES * STAGE_BYTES)   // 102400

__global__ void __launch_bounds__(256, 2)
gemm_loss_kernel(const float* __restrict__ wp) {
    extern __shared__ char smem[];
    const uint32_t sb = smem_u32(smem);
    const int tid  = threadIdx.x;
    const int wid  = tid >> 5;
    const int lane = tid & 31;
    const int wy   = wid >> 2;          // 0..1  (64-row slice)
    const int wx   = wid & 3;           // 0..3  (32-col slice)
    const int col0 = blockIdx.x * 128;
    const int row0 = blockIdx.y * 128;

    float* sh_einv = (float*)(smem + OFF_EINV);
    float* sh_esq  = (float*)(smem + OFF_ESQ);
    float* sh_cinv = (float*)(smem + OFF_CINV);
    float* sh_csq  = (float*)(smem + OFF_CSQ);
    float* sh_part = (float*)(smem + OFF_PART);

    if (tid < 128) {
        sh_einv[tid] = g_einv[row0 + tid];
        sh_esq[tid]  = g_esq[row0 + tid];
        sh_cinv[tid] = g_cinv[col0 + tid];
        sh_csq[tid]  = g_csq[col0 + tid];
    }

    const char* Ag0 = (const char*)(g_A8 + (size_t)row0 * D_DIM);
    const char* Bg0 = (const char*)(g_C8 + (size_t)col0 * D_DIM);
    auto load_stage = [&](int kt, int s) {
        uint32_t abase = sb + OFF_STAGE + s * STAGE_BYTES;
        uint32_t bbase = abase + A_BYTES;
        const char* Ag = Ag0 + kt * 128;
        const char* Bg = Bg0 + kt * 128;
#pragma unroll
        for (int t = 0; t < 4; t++) {
            int ch = tid + t * 256;
            int r = ch >> 3, c = ch & 7;
            uint32_t bo = r * 128 + c * 16;
            cp_async16(abase + swz(bo), Ag + (size_t)r * 512 + c * 16);
        }
#pragma unroll
        for (int t = 0; t < 4; t++) {
            int ch = tid + t * 256;
            int r = ch >> 3, c = ch & 7;
            uint32_t bo = r * 128 + c * 16;
            cp_async16(bbase + swz(bo), Bg + (size_t)r * 512 + c * 16);
        }
        cp_commit();
    };

    load_stage(0, 0);
    load_stage(1, 1);

    int acc[4][4][4];
#pragma unroll
    for (int i = 0; i < 4; i++)
#pragma unroll
        for (int j = 0; j < 4; j++)
#pragma unroll
            for (int k = 0; k < 4; k++) acc[i][j][k] = 0;

    const int lrow = lane & 15;
    const int lc16 = lane >> 4;
    const uint32_t aoff0 = (wy * 64 + lrow) * 128 + lc16 * 16;
    const uint32_t boff0 = (wx * 32 + lrow) * 128 + lc16 * 16;

#pragma unroll 1
    for (int kt = 0; kt < 4; kt++) {
        const int s = kt % STAGES;
        if (kt < 3) cp_wait<1>(); else cp_wait<0>();
        __syncthreads();

        uint32_t abase = sb + OFF_STAGE + s * STAGE_BYTES;
        uint32_t bbase = abase + A_BYTES;
#pragma unroll
        for (int kg = 0; kg < 4; kg++) {
            uint32_t a[4][4], b[2][4];
#pragma unroll
            for (int mt = 0; mt < 4; mt++)
                ldmx4(a[mt], abase + swz(aoff0 + mt * 2048 + kg * 32));
#pragma unroll
            for (int nb = 0; nb < 2; nb++)
                ldmx4(b[nb], bbase + swz(boff0 + nb * 2048 + kg * 32));
#pragma unroll
            for (int mt = 0; mt < 4; mt++)
#pragma unroll
                for (int nt = 0; nt < 4; nt++)
                    mma_s8(acc[mt][nt], a[mt], b[nt >> 1][nt & 1], b[nt >> 1][(nt & 1) + 2]);
        }

        if (kt + 2 < 4) load_stage(kt + 2, (kt + 2) % STAGES);
        else cp_commit();
    }
    __syncthreads();

    // ---- branchless softmax epilogue ----
    const float wv     = *wp;
    const float wl2    = wv * LOG2E;
    const float clamp2 = EPS * wl2;

    float tc2[8];
#pragma unroll
    for (int nt = 0; nt < 4; nt++)
#pragma unroll
        for (int j = 0; j < 2; j++) {
            int cl = wx * 32 + nt * 8 + (lane & 3) * 2 + j;
            tc2[nt * 2 + j] = sh_cinv[cl] * wl2 * INV_DOT;
        }

    const bool fixcta = ((int)blockIdx.x == ((int)blockIdx.y >> 5));

    float* part = sh_part + wx * 128;

#pragma unroll
    for (int mt = 0; mt < 4; mt++) {
#pragma unroll
        for (int half = 0; half < 2; half++) {
            int   rl   = wy * 64 + mt * 16 + (lane >> 2) + half * 8;
            float einv = sh_einv[rl];

            float rsum = 0.f;
#pragma unroll
            for (int nt = 0; nt < 4; nt++) {
#pragma unroll
                for (int j = 0; j < 2; j++) {
                    float v = __int2float_rn(acc[mt][nt][half * 2 + j]);
                    float u = fmaxf((v * einv) * tc2[nt * 2 + j], clamp2);
                    rsum += exp2_fast(u);
                }
            }

            if (fixcta) {
                int r   = row0 + rl;
                int clt = (r >> 5) - col0;        // target own column (0..127)
#pragma unroll
                for (int nt = 0; nt < 4; nt++) {
#pragma unroll
                    for (int j = 0; j < 2; j++) {
                        int cl_e = wx * 32 + nt * 8 + (lane & 3) * 2 + j;
                        if (cl_e == clt) {        // compile-time acc indices only
                            float v  = __int2float_rn(acc[mt][nt][half * 2 + j]);
                            float up = fmaxf((v * einv) * tc2[nt * 2 + j], clamp2);
                            float esq  = sh_esq[rl];
                            float vv   = v * INV_DOT;
                            float dl   = fmaf(32.f, vv, -esq) * (1.f / 31.f);
                            float clq  = (1024.f * sh_csq[clt] - 64.f * vv + esq) * (1.f / 961.f);
                            float cosv = dl * einv * rsqrtf(clq);
                            float u    = fmaxf(cosv * wl2, clamp2);
                            g_own[r]   = u;
                            rsum += exp2_fast(u) - exp2_fast(up);
                        }
                    }
                }
            }

            rsum += __shfl_xor_sync(0xffffffffu, rsum, 1);
            rsum += __shfl_xor_sync(0xffffffffu, rsum, 2);
            if ((lane & 3) == 0) part[rl] = rsum;
        }
    }
    __syncthreads();

    if (tid < 128) {
        g_Zp[(size_t)blockIdx.x * R_ROWS + row0 + tid] =
            sh_part[tid] + sh_part[128 + tid] + sh_part[256 + tid] + sh_part[384 + tid];
    }
}

// ---------------------------------------------------------------------------
// Kernel 3: single-launch loss reduction. 128 blocks x 256 threads.
// ---------------------------------------------------------------------------
__global__ void __launch_bounds__(256) loss_kernel(float* __restrict__ out) {
    const int tid = threadIdx.x;
    const int r   = blockIdx.x * 256 + tid;
    float z = 0.f;
#pragma unroll
    for (int p = 0; p < 8; p++) z += g_Zp[(size_t)p * R_ROWS + r];
    float s = logf(z) - g_own[r] * LN2F;

    __shared__ float sh[256];
    __shared__ bool  last;
    sh[tid] = s;
    __syncthreads();
    for (int off = 128; off > 0; off >>= 1) {
        if (tid < off) sh[tid] += sh[tid + off];
        __syncthreads();
    }
    if (tid == 0) {
        g_bsum[blockIdx.x] = sh[0];
        __threadfence();
        unsigned int t = atomicAdd(&g_count, 1u);
        last = (t == 127u);
    }
    __syncthreads();

    if (last) {
        float v = (tid < 128) ? g_bsum[tid] : 0.f;
#pragma unroll
        for (int off = 16; off > 0; off >>= 1) v += __shfl_xor_sync(0xffffffffu, v, off);
        __shared__ float sh2[8];
        if ((tid & 31) == 0) sh2[tid >> 5] = v;
        __syncthreads();
        if (tid == 0) {
            out[0] = sh2[0] + sh2[1] + sh2[2] + sh2[3];
            g_count = 0;                       // reset for next graph replay
        }
    }
}

// ---------------------------------------------------------------------------
extern "C" void kernel_launch(void* const* d_in, const int* in_sizes, int n_in,
                              void* d_out, int out_size) {
    const float* dvecs = (const float*)d_in[0];
    const float* w     = (const float*)d_in[1];
    float* out         = (float*)d_out;

    cudaFuncSetAttribute(prep_kernel,
                         cudaFuncAttributeMaxDynamicSharedMemorySize, P_SMEM_TOTAL);
    cudaFuncSetAttribute(gemm_loss_kernel,
                         cudaFuncAttributeMaxDynamicSharedMemorySize, SMEM_TOTAL);

    prep_kernel<<<N_SPK, 256, P_SMEM_TOTAL>>>(dvecs);
    gemm_loss_kernel<<<dim3(8, 256), 256, SMEM_TOTAL>>>(w);
    loss_kernel<<<128, 256>>>(out);
}

// round 17
// speedup vs baseline: 1.0049x; 1.0045x over previous
#include <cuda_runtime.h>
#include <cuda_bf16.h>
#include <math.h>
#include <stdint.h>

#define N_SPK 1024
#define M_UTT 32
#define D_DIM 512
#define R_ROWS (N_SPK * M_UTT)
#define EPS 1e-6f
#define LOG2E 1.4426950408889634f
#define LN2F 0.6931471805599453f
#define SA 25.0f                      // A quant scale (range +-5.08)
#define SC 127.0f                     // C quant scale
#define INV_DOT (1.0f / (SA * SC))

// ---------------- device scratch (no allocations allowed) ----------------
__device__ uint8_t g_A8[R_ROWS * D_DIM];          // 16 MB  int8 dvecs (x25)
__device__ uint8_t g_C8[N_SPK * D_DIM];           // 0.5 MB int8 centroids (x127)
__device__ float g_csq[N_SPK];
__device__ float g_cinv[N_SPK];
__device__ float g_esq[R_ROWS];
__device__ float g_einv[R_ROWS];
__device__ float g_Zp[8 * R_ROWS];                // per-col-tile softmax partials
__device__ float g_own[R_ROWS];                   // own-speaker w*cos*log2e
__device__ float g_bsum[128];                     // loss block partials
__device__ unsigned int g_count = 0;              // completion counter

// ---------------- PTX helpers ----------------
__device__ __forceinline__ uint32_t smem_u32(const void* p) {
    uint32_t a;
    asm("{ .reg .u64 t; cvta.to.shared.u64 t, %1; cvt.u32.u64 %0, t; }" : "=r"(a) : "l"(p));
    return a;
}
__device__ __forceinline__ void cp_async16(uint32_t dst, const void* src) {
    asm volatile("cp.async.cg.shared.global.L2::128B [%0], [%1], 16;\n" :: "r"(dst), "l"(src));
}
__device__ __forceinline__ void cp_commit() {
    asm volatile("cp.async.commit_group;\n" ::: "memory");
}
template <int N>
__device__ __forceinline__ void cp_wait() {
    asm volatile("cp.async.wait_group %0;\n" :: "n"(N) : "memory");
}
__device__ __forceinline__ void ldmx4(uint32_t* r, uint32_t addr) {
    asm volatile("ldmatrix.sync.aligned.m8n8.x4.shared.b16 {%0,%1,%2,%3}, [%4];"
                 : "=r"(r[0]), "=r"(r[1]), "=r"(r[2]), "=r"(r[3]) : "r"(addr));
}
// int8 IMMA: m16n8k32, s32 accumulate
__device__ __forceinline__ void mma_s8(int* c, const uint32_t* a, uint32_t b0, uint32_t b1) {
    asm volatile(
        "mma.sync.aligned.m16n8k32.row.col.s32.s8.s8.s32 "
        "{%0,%1,%2,%3}, {%4,%5,%6,%7}, {%8,%9}, {%0,%1,%2,%3};"
        : "+r"(c[0]), "+r"(c[1]), "+r"(c[2]), "+r"(c[3])
        : "r"(a[0]), "r"(a[1]), "r"(a[2]), "r"(a[3]), "r"(b0), "r"(b1));
}
__device__ __forceinline__ uint32_t swz(uint32_t bo) {   // SW128: bits[4:6] ^= bits[7:9]
    return bo ^ ((bo >> 3) & 0x70);
}
// saturating pack of 4 scaled floats -> 4 x s8 (byte0 = x)
__device__ __forceinline__ uint32_t packs8x4(float4 v, float s) {
    int ia = __float2int_rn(v.x * s);
    int ib = __float2int_rn(v.y * s);
    int ic = __float2int_rn(v.z * s);
    int id = __float2int_rn(v.w * s);
    uint32_t t, r;
    asm("cvt.pack.sat.s8.s32.b32 %0, %1, %2, %3;" : "=r"(t) : "r"(id), "r"(ic), "r"(0));
    asm("cvt.pack.sat.s8.s32.b32 %0, %1, %2, %3;" : "=r"(r) : "r"(ib), "r"(ia), "r"(t));
    return r;
}
__device__ __forceinline__ uint16_t packs8x2(float x, float y, float s) {
    int ia = __float2int_rn(x * s);
    int ib = __float2int_rn(y * s);
    uint32_t t;
    asm("cvt.pack.sat.s8.s32.b32 %0, %1, %2, %3;" : "=r"(t) : "r"(ib), "r"(ia), "r"(0));
    return (uint16_t)t;
}

// fast 2^x on the FMA pipe, x in ~[-8, 8].
// Bias folded into the magic constant: bits(x + (12582912+127)) << 23 gives the
// scale directly (1 SHF vs IADD+IADD+SHF). Bitwise identical to the old form.
__device__ __forceinline__ float exp2_fast(float x) {
    const float MAGIC = 12583039.0f;           // 12582912 + 127
    float z = x + MAGIC;                       // round-to-nearest, int in mantissa
    float t = z - MAGIC;                       // = round(x), exact
    float f = x - t;                           // f in [-0.5, 0.5]
    uint32_t s = __float_as_uint(z) << 23;     // (round(x)+127) << 23
    float p = 0.001333355814642844f;
    p = fmaf(p, f, 0.009618129107628477f);
    p = fmaf(p, f, 0.055504108664821580f);
    p = fmaf(p, f, 0.240226506959100700f);
    p = fmaf(p, f, 0.693147180559945300f);
    p = fmaf(p, f, 1.0f);
    return p * __uint_as_float(s);
}

// ---------------------------------------------------------------------------
// Kernel 1: fused prep via cp.async double-buffer (32KB smem -> 7 CTAs/SM,
// grid fits one wave). 4 K-stages of 8 rows x 2KB, consumed warp-per-row.
// ---------------------------------------------------------------------------
#define P_STAGE_BYTES 16384            // 8 rows x 2048 B
#define P_SMEM_TOTAL  32768            // 2 buffers

__global__ void __launch_bounds__(256) prep_kernel(const float* __restrict__ dvecs) {
    extern __shared__ char psm[];
    const uint32_t sb = smem_u32(psm);

    const int j    = blockIdx.x;
    const int tid  = threadIdx.x;
    const int wid  = tid >> 5;
    const int lane = tid & 31;

    const char* gsrc = (const char*)(dvecs + (size_t)j * M_UTT * D_DIM);

    auto load_stage = [&](int s, int buf) {
#pragma unroll
        for (int t = 0; t < 4; t++) {
            int idx = tid + t * 256;            // 1024 x 16B chunks per stage
            cp_async16(sb + buf * P_STAGE_BYTES + idx * 16,
                       gsrc + (size_t)s * P_STAGE_BYTES + idx * 16);
        }
        cp_commit();
    };

    load_stage(0, 0);
    load_stage(1, 1);

    float4 csum[4];
#pragma unroll
    for (int k = 0; k < 4; k++) csum[k] = make_float4(0.f, 0.f, 0.f, 0.f);
    float nrm[4] = {0.f, 0.f, 0.f, 0.f};

#pragma unroll
    for (int s = 0; s < 4; s++) {
        if (s < 3) cp_wait<1>(); else cp_wait<0>();
        __syncthreads();

        const int buf = s & 1;
        const int m   = s * 8 + wid;
        const float4* srow = (const float4*)(psm + buf * P_STAGE_BYTES + wid * 2048);
        uint32_t* dst = (uint32_t*)(g_A8 + (size_t)(j * M_UTT + m) * D_DIM);
#pragma unroll
        for (int k = 0; k < 4; k++) {
            float4 v = srow[lane + k * 32];
            nrm[s] = fmaf(v.x, v.x, fmaf(v.y, v.y, fmaf(v.z, v.z, fmaf(v.w, v.w, nrm[s]))));
            csum[k].x += v.x; csum[k].y += v.y;
            csum[k].z += v.z; csum[k].w += v.w;
            dst[lane + k * 32] = packs8x4(v, SA);
        }
        __syncthreads();                        // buffer drained before refill
        if (s + 2 < 4) load_stage(s + 2, buf);
    }

    // per-row norm reductions (warp w owns rows 8s+w)
#pragma unroll
    for (int s = 0; s < 4; s++) {
        float t = nrm[s];
#pragma unroll
        for (int off = 16; off > 0; off >>= 1) t += __shfl_xor_sync(0xffffffffu, t, off);
        if (lane == 0) {
            const int row = j * M_UTT + s * 8 + wid;
            g_esq[row]  = t;
            g_einv[row] = rsqrtf(t);
        }
    }
    __syncthreads();                   // all stage reads done -> overlay safe

    // centroid: per-warp partials into overlay smem (both buffers reused)
    float* shc = (float*)psm;          // 8 x 512 floats = 16 KB (buffer 0)
    float* shr = (float*)(psm + 16384);  // 1 KB (buffer 1)
    float4* myrow = (float4*)(shc + wid * 512);
#pragma unroll
    for (int k = 0; k < 4; k++) myrow[lane + k * 32] = csum[k];
    __syncthreads();

    float2 tot = make_float2(0.f, 0.f);
#pragma unroll
    for (int w = 0; w < 8; w++) {
        float2 v = ((float2*)(shc + w * 512))[tid];
        tot.x += v.x;
        tot.y += v.y;
    }
    float cx = tot.x * (1.0f / M_UTT);
    float cy = tot.y * (1.0f / M_UTT);
    ((uint16_t*)(g_C8 + (size_t)j * D_DIM))[tid] = packs8x2(cx, cy, SC);

    shr[tid] = cx * cx + cy * cy;
    __syncthreads();
    for (int off = 128; off > 0; off >>= 1) {
        if (tid < off) shr[tid] += shr[tid + off];
        __syncthreads();
    }
    if (tid == 0) {
        g_csq[j]  = shr[0];
        g_cinv[j] = rsqrtf(shr[0]);
    }
}

// ---------------------------------------------------------------------------
// Kernel 2: int8 IMMA GEMM + branchless softmax epilogue (structure unchanged;
// exp2_fast now 2 ops cheaper per element).
// ---------------------------------------------------------------------------
#define STAGES 3
#define A_BYTES 16384
#define B_BYTES 16384
#define STAGE_BYTES (A_BYTES + B_BYTES)
#define OFF_EINV  0
#define OFF_ESQ   512
#define OFF_CINV  1024
#define OFF_CSQ   1536
#define OFF_PART  2048                 // 4 x 128 floats
#define OFF_STAGE 4096
#define SMEM_TOTAL (OFF_STAGE + STAGES * STAGE_BYTES)   // 102400

__global__ void __launch_bounds__(256, 2)
gemm_loss_kernel(const float* __restrict__ wp) {
    extern __shared__ char smem[];
    const uint32_t sb = smem_u32(smem);
    const int tid  = threadIdx.x;
    const int wid  = tid >> 5;
    const int lane = tid & 31;
    const int wy   = wid >> 2;          // 0..1  (64-row slice)
    const int wx   = wid & 3;           // 0..3  (32-col slice)
    const int col0 = blockIdx.x * 128;
    const int row0 = blockIdx.y * 128;

    float* sh_einv = (float*)(smem + OFF_EINV);
    float* sh_esq  = (float*)(smem + OFF_ESQ);
    float* sh_cinv = (float*)(smem + OFF_CINV);
    float* sh_csq  = (float*)(smem + OFF_CSQ);
    float* sh_part = (float*)(smem + OFF_PART);

    if (tid < 128) {
        sh_einv[tid] = g_einv[row0 + tid];
        sh_esq[tid]  = g_esq[row0 + tid];
        sh_cinv[tid] = g_cinv[col0 + tid];
        sh_csq[tid]  = g_csq[col0 + tid];
    }

    const char* Ag0 = (const char*)(g_A8 + (size_t)row0 * D_DIM);
    const char* Bg0 = (const char*)(g_C8 + (size_t)col0 * D_DIM);
    auto load_stage = [&](int kt, int s) {
        uint32_t abase = sb + OFF_STAGE + s * STAGE_BYTES;
        uint32_t bbase = abase + A_BYTES;
        const char* Ag = Ag0 + kt * 128;
        const char* Bg = Bg0 + kt * 128;
#pragma unroll
        for (int t = 0; t < 4; t++) {
            int ch = tid + t * 256;
            int r = ch >> 3, c = ch & 7;
            uint32_t bo = r * 128 + c * 16;
            cp_async16(abase + swz(bo), Ag + (size_t)r * 512 + c * 16);
        }
#pragma unroll
        for (int t = 0; t < 4; t++) {
            int ch = tid + t * 256;
            int r = ch >> 3, c = ch & 7;
            uint32_t bo = r * 128 + c * 16;
            cp_async16(bbase + swz(bo), Bg + (size_t)r * 512 + c * 16);
        }
        cp_commit();
    };

    load_stage(0, 0);
    load_stage(1, 1);

    int acc[4][4][4];
#pragma unroll
    for (int i = 0; i < 4; i++)
#pragma unroll
        for (int j = 0; j < 4; j++)
#pragma unroll
            for (int k = 0; k < 4; k++) acc[i][j][k] = 0;

    const int lrow = lane & 15;
    const int lc16 = lane >> 4;
    const uint32_t aoff0 = (wy * 64 + lrow) * 128 + lc16 * 16;
    const uint32_t boff0 = (wx * 32 + lrow) * 128 + lc16 * 16;

#pragma unroll 1
    for (int kt = 0; kt < 4; kt++) {
        const int s = kt % STAGES;
        if (kt < 3) cp_wait<1>(); else cp_wait<0>();
        __syncthreads();

        uint32_t abase = sb + OFF_STAGE + s * STAGE_BYTES;
        uint32_t bbase = abase + A_BYTES;
#pragma unroll
        for (int kg = 0; kg < 4; kg++) {
            uint32_t a[4][4], b[2][4];
#pragma unroll
            for (int mt = 0; mt < 4; mt++)
                ldmx4(a[mt], abase + swz(aoff0 + mt * 2048 + kg * 32));
#pragma unroll
            for (int nb = 0; nb < 2; nb++)
                ldmx4(b[nb], bbase + swz(boff0 + nb * 2048 + kg * 32));
#pragma unroll
            for (int mt = 0; mt < 4; mt++)
#pragma unroll
                for (int nt = 0; nt < 4; nt++)
                    mma_s8(acc[mt][nt], a[mt], b[nt >> 1][nt & 1], b[nt >> 1][(nt & 1) + 2]);
        }

        if (kt + 2 < 4) load_stage(kt + 2, (kt + 2) % STAGES);
        else cp_commit();
    }
    __syncthreads();

    // ---- branchless softmax epilogue ----
    const float wv     = *wp;
    const float wl2    = wv * LOG2E;
    const float clamp2 = EPS * wl2;

    float tc2[8];
#pragma unroll
    for (int nt = 0; nt < 4; nt++)
#pragma unroll
        for (int j = 0; j < 2; j++) {
            int cl = wx * 32 + nt * 8 + (lane & 3) * 2 + j;
            tc2[nt * 2 + j] = sh_cinv[cl] * wl2 * INV_DOT;
        }

    const bool fixcta = ((int)blockIdx.x == ((int)blockIdx.y >> 5));

    float* part = sh_part + wx * 128;

#pragma unroll
    for (int mt = 0; mt < 4; mt++) {
#pragma unroll
        for (int half = 0; half < 2; half++) {
            int   rl   = wy * 64 + mt * 16 + (lane >> 2) + half * 8;
            float einv = sh_einv[rl];

            float rsum = 0.f;
#pragma unroll
            for (int nt = 0; nt < 4; nt++) {
#pragma unroll
                for (int j = 0; j < 2; j++) {
                    float v = __int2float_rn(acc[mt][nt][half * 2 + j]);
                    float u = fmaxf((v * einv) * tc2[nt * 2 + j], clamp2);
                    rsum += exp2_fast(u);
                }
            }

            if (fixcta) {
                int r   = row0 + rl;
                int clt = (r >> 5) - col0;        // target own column (0..127)
#pragma unroll
                for (int nt = 0; nt < 4; nt++) {
#pragma unroll
                    for (int j = 0; j < 2; j++) {
                        int cl_e = wx * 32 + nt * 8 + (lane & 3) * 2 + j;
                        if (cl_e == clt) {        // compile-time acc indices only
                            float v  = __int2float_rn(acc[mt][nt][half * 2 + j]);
                            float up = fmaxf((v * einv) * tc2[nt * 2 + j], clamp2);
                            float esq  = sh_esq[rl];
                            float vv   = v * INV_DOT;
                            float dl   = fmaf(32.f, vv, -esq) * (1.f / 31.f);
                            float clq  = (1024.f * sh_csq[clt] - 64.f * vv + esq) * (1.f / 961.f);
                            float cosv = dl * einv * rsqrtf(clq);
                            float u    = fmaxf(cosv * wl2, clamp2);
                            g_own[r]   = u;
                            rsum += exp2_fast(u) - exp2_fast(up);
                        }
                    }
                }
            }

            rsum += __shfl_xor_sync(0xffffffffu, rsum, 1);
            rsum += __shfl_xor_sync(0xffffffffu, rsum, 2);
            if ((lane & 3) == 0) part[rl] = rsum;
        }
    }
    __syncthreads();

    if (tid < 128) {
        g_Zp[(size_t)blockIdx.x * R_ROWS + row0 + tid] =
            sh_part[tid] + sh_part[128 + tid] + sh_part[256 + tid] + sh_part[384 + tid];
    }
}

// ---------------------------------------------------------------------------
// Kernel 3: single-launch loss reduction. 128 blocks x 256 threads.
// ---------------------------------------------------------------------------
__global__ void __launch_bounds__(256) loss_kernel(float* __restrict__ out) {
    const int tid = threadIdx.x;
    const int r   = blockIdx.x * 256 + tid;
    float z = 0.f;
#pragma unroll
    for (int p = 0; p < 8; p++) z += g_Zp[(size_t)p * R_ROWS + r];
    float s = logf(z) - g_own[r] * LN2F;

    __shared__ float sh[256];
    __shared__ bool  last;
    sh[tid] = s;
    __syncthreads();
    for (int off = 128; off > 0; off >>= 1) {
        if (tid < off) sh[tid] += sh[tid + off];
        __syncthreads();
    }
    if (tid == 0) {
        g_bsum[blockIdx.x] = sh[0];
        __threadfence();
        unsigned int t = atomicAdd(&g_count, 1u);
        last = (t == 127u);
    }
    __syncthreads();

    if (last) {
        float v = (tid < 128) ? g_bsum[tid] : 0.f;
#pragma unroll
        for (int off = 16; off > 0; off >>= 1) v += __shfl_xor_sync(0xffffffffu, v, off);
        __shared__ float sh2[8];
        if ((tid & 31) == 0) sh2[tid >> 5] = v;
        __syncthreads();
        if (tid == 0) {
            out[0] = sh2[0] + sh2[1] + sh2[2] + sh2[3];
            g_count = 0;                       // reset for next graph replay
        }
    }
}

// ---------------------------------------------------------------------------
extern "C" void kernel_launch(void* const* d_in, const int* in_sizes, int n_in,
                              void* d_out, int out_size) {
    const float* dvecs = (const float*)d_in[0];
    const float* w     = (const float*)d_in[1];
    float* out         = (float*)d_out;

    cudaFuncSetAttribute(prep_kernel,
                         cudaFuncAttributeMaxDynamicSharedMemorySize, P_SMEM_TOTAL);
    cudaFuncSetAttribute(gemm_loss_kernel,
                         cudaFuncAttributeMaxDynamicSharedMemorySize, SMEM_TOTAL);

    prep_kernel<<<N_SPK, 256, P_SMEM_TOTAL>>>(dvecs);
    gemm_loss_kernel<<<dim3(8, 256), 256, SMEM_TOTAL>>>(w);
    loss_kernel<<<128, 256>>>(out);
}